// round 10
// baseline (speedup 1.0000x reference)
#include <cuda_runtime.h>

#define KB      16
#define NPARAMS 63
#define TPB     128
#define WSZ     32
#define SLICE   (32 * 33)     // 32 rows x 33 floats (padded stride) — phase-1 only
#define EPSV    1e-6f

__global__ void __launch_bounds__(TPB, 10) lrs_kernel(
    const float* __restrict__ inputs,
    const float* __restrict__ params,
    float* __restrict__ out,
    int n_rows)
{
    // 4 warps x (32 rows x 33 floats) = 16896 B / block
    __shared__ float sp[(TPB / WSZ) * SLICE];

    const int wid  = threadIdx.x >> 5;
    const int lane = threadIdx.x & 31;
    const int grow0 = (blockIdx.x * (TPB / WSZ) + wid) * WSZ;  // warp's first row

    float* sl = sp + wid * SLICE;
    const float* gp = params + (size_t)grow0 * NPARAMS;

    // ---- Stage w,h (params 0..31) for this warp's 32 rows, coalesced ----
#pragma unroll
    for (int j = 0; j < 32; j++)
        sl[j * 33 + lane] = gp[j * NPARAMS + lane];
    __syncwarp();

    const int row = grow0 + lane;
    const float x = inputs[row];
    const float* p = sl + lane * 33;   // bank (lane+k)%32 -> conflict-free

    // ---- widths softmax + knots + bin search (fused, monotone knots) ----
    float ew[KB];
    float sw = 0.f;
#pragma unroll
    for (int k = 0; k < KB; k++) { ew[k] = __expf(p[k]); sw += ew[k]; }
    const float wfac = __fdividef(1.0f - 0.001f * KB, sw);

    int   idx = 0;
    float cw  = -3.f;
    float cwn = 0.f;
    {
        float c = 0.f;
        bool psel = true;
#pragma unroll
        for (int k = 1; k <= KB; k++) {
            c += fmaf(wfac, ew[k - 1], 0.001f);
            float kn = (k == KB) ? 3.f : fmaf(6.f, c, -3.f);
            if (psel) cwn = kn;
            bool sel = (k < KB) && (kn + EPSV <= x);
            if (sel) { idx = k; cw = kn; }
            psel = sel;
        }
    }
    const float wid_w = cwn - cw;

    // ---- Gather the 3 needed tail params NOW (latency hidden by heights) ----
    // d_lo raw = params[row][31+idx]  (unused when idx==0; 31+idx is in-row, safe)
    // d_hi raw = params[row][32+idx]  (unused when idx==15; 47 is in-row, safe)
    // lam  raw = params[row][47+idx]
    const float* rowp = params + (size_t)row * NPARAMS;
    const float dv0 = __ldg(rowp + 31 + idx);
    const float dv1 = __ldg(rowp + 32 + idx);
    const float lv  = __ldg(rowp + 47 + idx);

    // ---- heights softmax + knots, select ya, yb (independent of gathers) ----
    float eh[KB];
    float sh = 0.f;
#pragma unroll
    for (int k = 0; k < KB; k++) { eh[k] = __expf(p[16 + k]); sh += eh[k]; }
    const float hfac = __fdividef(1.0f - 0.001f * KB, sh);

    float ya = -3.f, yb = 0.f;
    {
        float c = 0.f;
        float prev = -3.f;
#pragma unroll
        for (int k = 1; k <= KB; k++) {
            c += fmaf(hfac, eh[k - 1], 0.001f);
            float kn = (k == KB) ? 3.f : fmaf(6.f, c, -3.f);
            if (k - 1 == idx) { ya = prev; yb = kn; }
            prev = kn;
        }
    }

    // ---- activations on just the 3 gathered values ----
    const float d_lo = (idx == 0)  ? 0.999f : (__logf(1.f + __expf(dv0)) + 0.001f);
    const float d_hi = (idx == 15) ? 0.999f : (__logf(1.f + __expf(dv1)) + 0.001f);
    const float sig  = __fdividef(1.f, 1.f + __expf(-lv));
    const float lam  = fmaf(0.95f, sig, 0.025f);

    // ---- linear rational spline evaluation ----
    const float hsel   = yb - ya;
    const float dinv   = __fdividef(wid_w, hsel);        // 1/delta
    const float wb     = __fsqrt_rn(__fdividef(d_lo, d_hi));
    const float lwb    = lam * wb;
    const float wc     = (lam * d_lo + (wb - lwb) * d_hi) * dinv;
    const float l1     = 1.f - lam;
    const float yc     = __fdividef(lwb * yb + l1 * ya, l1 + lwb);
    const float theta  = __fdividef(x - cw, wid_w);
    const bool  ind    = theta <= lam;
    const float ltheta = lam - theta;
    const float wcyc   = wc * yc;
    const float wcyct  = wcyc * theta;
    const float num    = ind ? fmaf(ya, ltheta, wcyct)
                             : ((wcyc - wcyct) - wb * yb * ltheta);
    const float wcth   = wc * theta;
    const float den    = ind ? (wcth + ltheta)
                             : ((wc - wcth) - wb * ltheta);
    float outv = __fdividef(num, den);

    const float dnum = __fdividef(wc * (ind ? lam * (yc - ya)
                                            : (wb - lwb) * (yb - yc)), wid_w);
    float lad = __logf(dnum) - 2.f * __logf(fabsf(den));

    const bool outside = (x < -3.f) || (x > 3.f);
    if (outside) { outv = x; lad = 0.f; }

    out[row]          = outv;
    out[n_rows + row] = lad;
}

extern "C" void kernel_launch(void* const* d_in, const int* in_sizes, int n_in,
                              void* d_out, int out_size)
{
    const float* inputs = (const float*)d_in[0];
    const float* params = (const float*)d_in[1];
    float* out = (float*)d_out;
    const int n = in_sizes[0];            // 1048576 rows
    const int blocks = n / TPB;
    lrs_kernel<<<blocks, TPB>>>(inputs, params, out, n);
}